// round 8
// baseline (speedup 1.0000x reference)
#include <cuda_runtime.h>

// PairTabModel: atomic energy via cubic-spline table lookup over neighbor lists.
// Shapes: coord (8,8192,3) f32, atype (8,8192) i32, nlist (8,4096,256) i32,
//         tab (4,4,1024,4) f32 -> out (8,4096) f32.
//
// Numerics must ulp-match the XLA reference (random/discontinuous spline
// coefficients make the knot index ulp-sensitive). Established by rel_err
// triangulation over R1-R7:
//   * uu = rr * 50.0f          (div-by-const -> mul-by-reciprocal; PROVEN)
//   * squared distance: 4-lane shuffle-tree horizontal reduce with zero pad,
//       s = RN(dx^2 + dz^2) + RN(dy^2 + 0) = (dx^2 + dz^2) + dy^2
//     -- the only distance-1-from-plain form consistent with ALL seven
//        measured variants (plain 12.7u, right 20.2u, fmaA 23.7u,
//        fmaB 21.8u, outer-fma 22.3u, div +26u).
//   * sqrt correctly rounded (sqrt.rn).

static constexpr int NFRAMES = 8;
static constexpr int NLOC    = 4096;
static constexpr int NALL    = 8192;
static constexpr int NNEI    = 256;
static constexpr int NTYPES  = 4;
static constexpr int NSPLINE = 1024;

__global__ __launch_bounds__(256, 8)
void pairtab_kernel(const float*  __restrict__ coord,   // (NFRAMES, NALL, 3)
                    const int*    __restrict__ atype,   // (NFRAMES, NALL)
                    const int*    __restrict__ nlist,   // (NFRAMES, NLOC, NNEI)
                    const float4* __restrict__ tab,     // (NTYPES, NTYPES, NSPLINE) of float4
                    float*        __restrict__ out)     // (NFRAMES, NLOC)
{
    const int gid = blockIdx.x;            // f * NLOC + i
    const int f   = gid >> 12;             // / 4096
    const int i   = gid & (NLOC - 1);
    const int tid = threadIdx.x;

    const float* cb = coord + (size_t)f * NALL * 3;
    const int*   ab = atype + (size_t)f * NALL;

    // Center atom (broadcast load, L1-hit for all threads)
    const float cix = __ldg(&cb[3 * i + 0]);
    const float ciy = __ldg(&cb[3 * i + 1]);
    const float ciz = __ldg(&cb[3 * i + 2]);
    const int   it  = __ldg(&ab[i]);

    // One neighbor per thread; nlist read is fully coalesced.
    const int n     = __ldg(&nlist[(size_t)gid * NNEI + tid]);
    const bool valid = (n != -1);
    const int nm    = (n < 0) ? 0 : n;

    // Gathered neighbor coord (random within 96 KB/frame -> L2 resident)
    const float cjx = __ldg(&cb[3 * nm + 0]);
    const float cjy = __ldg(&cb[3 * nm + 1]);
    const float cjz = __ldg(&cb[3 * nm + 2]);
    const int   jt  = __ldg(&ab[nm]);

    // Shuffle-tree horizontal reduce: (dx^2 + dz^2) + dy^2. No contraction.
    const float dx = __fsub_rn(cix, cjx);
    const float dy = __fsub_rn(ciy, cjy);
    const float dz = __fsub_rn(ciz, cjz);
    const float s  = __fadd_rn(__fadd_rn(__fmul_rn(dx, dx), __fmul_rn(dz, dz)),
                               __fmul_rn(dy, dy));
    const float rr = __fsqrt_rn(s);

    // divide-by-const -> multiply by reciprocal; 1/0.02f == 50.0f exactly.
    const float uu = valid ? __fmul_rn(rr, 50.0f) : (float)(NSPLINE + 1);

    const int   idx  = (int)uu;                       // truncation, uu >= 0
    const float frac = __fsub_rn(uu, (float)idx);
    const int   clip = (idx > NSPLINE - 1) ? (NSPLINE - 1) : (idx < 0 ? 0 : idx);

    float4 c;
    if (idx >= NSPLINE) {
        c = make_float4(0.f, 0.f, 0.f, 0.f);
    } else {
        c = __ldg(&tab[((size_t)it * NTYPES + jt) * NSPLINE + clip]);
    }

    // ener = ((c3*frac + c2)*frac + c1)*frac + c0  (smooth path; fma is fine)
    float ener = fmaf(fmaf(fmaf(c.w, frac, c.z), frac, c.y), frac, c.x);
    if (!valid) ener = 0.f;

    // Block reduction over 256 threads (8 warps)
    #pragma unroll
    for (int off = 16; off > 0; off >>= 1)
        ener += __shfl_down_sync(0xFFFFFFFFu, ener, off);

    __shared__ float warp_sums[8];
    const int lane = tid & 31;
    const int wid  = tid >> 5;
    if (lane == 0) warp_sums[wid] = ener;
    __syncthreads();

    if (wid == 0) {
        float v = (lane < 8) ? warp_sums[lane] : 0.f;
        #pragma unroll
        for (int off = 4; off > 0; off >>= 1)
            v += __shfl_down_sync(0xFFFFFFFFu, v, off);
        if (lane == 0) out[gid] = 0.5f * v;
    }
}

extern "C" void kernel_launch(void* const* d_in, const int* in_sizes, int n_in,
                              void* d_out, int out_size)
{
    const float*  coord = (const float*)d_in[0];
    const int*    atype = (const int*)d_in[1];
    const int*    nlist = (const int*)d_in[2];
    const float4* tab   = (const float4*)d_in[3];
    float*        out   = (float*)d_out;

    pairtab_kernel<<<NFRAMES * NLOC, 256>>>(coord, atype, nlist, tab, out);
}

// round 9
// speedup vs baseline: 1.3299x; 1.3299x over previous
#include <cuda_runtime.h>

// PairTabModel: atomic energy via cubic-spline table lookup over neighbor lists.
// Shapes: coord (8,8192,3) f32, atype (8,8192) i32, nlist (8,4096,256) i32,
//         tab (4,4,1024,4) f32 -> out (8,4096) f32.
//
// Numerics (ulp-matched to reference, validated R1-R8, rel_err 1.1e-7):
//   * s = (dx^2 + dz^2) + dy^2   (shuffle-tree horizontal reduce order)
//   * uu = rr * 50.0f            (div-by-const -> mul-by-reciprocal)
//   * sqrt.rn
// DO NOT alter the order/rounding of these ops: the spline table is random,
// so the knot index is ulp-sensitive.
//
// Perf structure (R8 ncu: L1=81% bottleneck from divergent scalar gathers):
// pack (x,y,z,atype) into one float4 so the neighbor gather is a single
// LDG.128 instead of 4 divergent loads -> ~2.4x fewer L1tex wavefronts.

static constexpr int NFRAMES = 8;
static constexpr int NLOC    = 4096;
static constexpr int NALL    = 8192;
static constexpr int NNEI    = 256;
static constexpr int NTYPES  = 4;
static constexpr int NSPLINE = 1024;

// Static scratch: packed (x, y, z, atype-as-float-bits) per atom. 1 MB.
__device__ float4 g_packed[NFRAMES * NALL];

__global__ __launch_bounds__(256)
void pack_kernel(const float* __restrict__ coord,   // (NFRAMES, NALL, 3)
                 const int*   __restrict__ atype)   // (NFRAMES, NALL)
{
    const int a = blockIdx.x * 256 + threadIdx.x;   // 0 .. NFRAMES*NALL-1
    const float x = coord[3 * a + 0];
    const float y = coord[3 * a + 1];
    const float z = coord[3 * a + 2];
    const int   t = atype[a];
    g_packed[a] = make_float4(x, y, z, __int_as_float(t));
}

__global__ __launch_bounds__(256, 8)
void pairtab_kernel(const int*    __restrict__ nlist,   // (NFRAMES, NLOC, NNEI)
                    const float4* __restrict__ tab,     // (NTYPES, NTYPES, NSPLINE) of float4
                    float*        __restrict__ out)     // (NFRAMES, NLOC)
{
    const int gid = blockIdx.x;            // f * NLOC + i
    const int f   = gid >> 12;             // / 4096
    const int i   = gid & (NLOC - 1);
    const int tid = threadIdx.x;

    const float4* pb = g_packed + (size_t)f * NALL;

    // Center atom (broadcast LDG.128, L1-hit for all threads)
    const float4 pi = __ldg(&pb[i]);
    const int    it = __float_as_int(pi.w);

    // One neighbor per thread; nlist read is fully coalesced.
    const int n     = __ldg(&nlist[(size_t)gid * NNEI + tid]);
    const bool valid = (n != -1);
    const int nm    = (n < 0) ? 0 : n;

    // Single 16B gather: coords + type in one LDG.128.
    const float4 pj = __ldg(&pb[nm]);
    const int    jt = __float_as_int(pj.w);

    // Shuffle-tree horizontal reduce: (dx^2 + dz^2) + dy^2. No contraction.
    const float dx = __fsub_rn(pi.x, pj.x);
    const float dy = __fsub_rn(pi.y, pj.y);
    const float dz = __fsub_rn(pi.z, pj.z);
    const float s  = __fadd_rn(__fadd_rn(__fmul_rn(dx, dx), __fmul_rn(dz, dz)),
                               __fmul_rn(dy, dy));
    const float rr = __fsqrt_rn(s);

    // divide-by-const -> multiply by reciprocal; 1/0.02f == 50.0f exactly.
    const float uu = valid ? __fmul_rn(rr, 50.0f) : (float)(NSPLINE + 1);

    const int   idx  = (int)uu;                       // truncation, uu >= 0
    const float frac = __fsub_rn(uu, (float)idx);
    const int   clip = (idx > NSPLINE - 1) ? (NSPLINE - 1) : (idx < 0 ? 0 : idx);

    float4 c;
    if (idx >= NSPLINE) {
        c = make_float4(0.f, 0.f, 0.f, 0.f);
    } else {
        c = __ldg(&tab[((size_t)it * NTYPES + jt) * NSPLINE + clip]);
    }

    // ener = ((c3*frac + c2)*frac + c1)*frac + c0  (smooth path; fma is fine)
    float ener = fmaf(fmaf(fmaf(c.w, frac, c.z), frac, c.y), frac, c.x);
    if (!valid) ener = 0.f;

    // Block reduction over 256 threads (8 warps)
    #pragma unroll
    for (int off = 16; off > 0; off >>= 1)
        ener += __shfl_down_sync(0xFFFFFFFFu, ener, off);

    __shared__ float warp_sums[8];
    const int lane = tid & 31;
    const int wid  = tid >> 5;
    if (lane == 0) warp_sums[wid] = ener;
    __syncthreads();

    if (wid == 0) {
        float v = (lane < 8) ? warp_sums[lane] : 0.f;
        #pragma unroll
        for (int off = 4; off > 0; off >>= 1)
            v += __shfl_down_sync(0xFFFFFFFFu, v, off);
        if (lane == 0) out[gid] = 0.5f * v;
    }
}

extern "C" void kernel_launch(void* const* d_in, const int* in_sizes, int n_in,
                              void* d_out, int out_size)
{
    const float*  coord = (const float*)d_in[0];
    const int*    atype = (const int*)d_in[1];
    const int*    nlist = (const int*)d_in[2];
    const float4* tab   = (const float4*)d_in[3];
    float*        out   = (float*)d_out;

    pack_kernel<<<(NFRAMES * NALL) / 256, 256>>>(coord, atype);
    pairtab_kernel<<<NFRAMES * NLOC, 256>>>(nlist, tab, out);
}

// round 10
// speedup vs baseline: 1.7886x; 1.3449x over previous
#include <cuda_runtime.h>

// PairTabModel: atomic energy via cubic-spline table lookup over neighbor lists.
// Shapes: coord (8,8192,3) f32, atype (8,8192) i32, nlist (8,4096,256) i32,
//         tab (4,4,1024,4) f32 -> out (8,4096) f32.
//
// Numerics (ulp-matched to reference, validated R1-R8, rel_err 1.1e-7):
//   * s = (dx^2 + dz^2) + dy^2   (shuffle-tree horizontal reduce order)
//   * uu = rr * 50.0f            (div-by-const -> mul-by-reciprocal)
//   * sqrt.rn
// DO NOT alter the order/rounding of these ops: the spline table is random,
// so the knot index is ulp-sensitive. (Final per-atom sum is smooth; its
// order may change freely.)
//
// Perf structure (R9 ncu: L1=86%, dur == L1tex-wavefront floor at ~65 wf per
// warp-iter): stage the whole frame's packed atoms (128 KB) in shared memory
// so the coordinate gather becomes LDS.128 (bank-conflict pipe, ~9 cyc/warp)
// instead of ~32 L1tex wavefronts. L1 keeps only tab gather + nlist stream.

static constexpr int NFRAMES = 8;
static constexpr int NLOC    = 4096;
static constexpr int NALL    = 8192;
static constexpr int NNEI    = 256;
static constexpr int NTYPES  = 4;
static constexpr int NSPLINE = 1024;

static constexpr int THREADS          = 1024;               // 32 warps
static constexpr int BLOCKS_PER_FRAME = 16;
static constexpr int ATOMS_PER_BLOCK  = NLOC / BLOCKS_PER_FRAME;  // 256
static constexpr int ATOMS_PER_WARP   = ATOMS_PER_BLOCK / 32;     // 8
static constexpr unsigned SMEM_BYTES  = NALL * sizeof(float4);    // 128 KB

__global__ __launch_bounds__(THREADS, 1)
void pairtab_kernel(const float*  __restrict__ coord,   // (NFRAMES, NALL, 3)
                    const int*    __restrict__ atype,   // (NFRAMES, NALL)
                    const int*    __restrict__ nlist,   // (NFRAMES, NLOC, NNEI)
                    const float4* __restrict__ tab,     // (NTYPES, NTYPES, NSPLINE) of float4
                    float*        __restrict__ out)     // (NFRAMES, NLOC)
{
    extern __shared__ float4 s_packed[];                 // [NALL]

    const int tid  = threadIdx.x;
    const int lane = tid & 31;
    const int w    = tid >> 5;
    const int f    = blockIdx.x / BLOCKS_PER_FRAME;
    const int a0   = (blockIdx.x % BLOCKS_PER_FRAME) * ATOMS_PER_BLOCK;

    // Stage the whole frame: packed (x,y,z,atype) per atom. Coalesced.
    {
        const float* cb = coord + (size_t)f * NALL * 3;
        const int*   ab = atype + (size_t)f * NALL;
        #pragma unroll
        for (int a = tid; a < NALL; a += THREADS) {
            s_packed[a] = make_float4(cb[3 * a + 0], cb[3 * a + 1],
                                      cb[3 * a + 2], __int_as_float(ab[a]));
        }
    }
    __syncthreads();

    // Each warp: 8 atoms, 256 neighbors each (8 chunks of 32 lanes).
    #pragma unroll
    for (int k = 0; k < ATOMS_PER_WARP; ++k) {
        const int a  = a0 + w * ATOMS_PER_WARP + k;      // this warp's atom
        const float4 pi = s_packed[a];                   // LDS broadcast
        const int    it = __float_as_int(pi.w);
        const int* nrow = nlist + ((size_t)f * NLOC + a) * NNEI;
        const float4* tabi = tab + (size_t)it * NTYPES * NSPLINE;

        float acc = 0.f;
        #pragma unroll
        for (int c = 0; c < NNEI / 32; ++c) {
            const int n     = __ldg(&nrow[c * 32 + lane]);   // coalesced
            const bool valid = (n != -1);
            const int nm    = (n < 0) ? 0 : n;

            const float4 pj = s_packed[nm];              // LDS.128 gather
            const int    jt = __float_as_int(pj.w);

            // Shuffle-tree reduce order: (dx^2 + dz^2) + dy^2. No contraction.
            const float dx = __fsub_rn(pi.x, pj.x);
            const float dy = __fsub_rn(pi.y, pj.y);
            const float dz = __fsub_rn(pi.z, pj.z);
            const float s  = __fadd_rn(__fadd_rn(__fmul_rn(dx, dx),
                                                 __fmul_rn(dz, dz)),
                                       __fmul_rn(dy, dy));
            const float rr = __fsqrt_rn(s);

            // div-by-const -> mul by reciprocal; 1/0.02f == 50.0f exactly.
            const float uu = valid ? __fmul_rn(rr, 50.0f) : (float)(NSPLINE + 1);

            const int   idx  = (int)uu;                  // truncation, uu >= 0
            const float frac = __fsub_rn(uu, (float)idx);
            const int   clip = (idx > NSPLINE - 1) ? (NSPLINE - 1)
                                                   : (idx < 0 ? 0 : idx);

            float4 cc;
            if (idx >= NSPLINE) {
                cc = make_float4(0.f, 0.f, 0.f, 0.f);
            } else {
                cc = __ldg(&tabi[(size_t)jt * NSPLINE + clip]);  // L1/L2 gather
            }

            float ener = fmaf(fmaf(fmaf(cc.w, frac, cc.z), frac, cc.y), frac, cc.x);
            if (!valid) ener = 0.f;
            acc += ener;                                 // smooth sum
        }

        // Warp reduction over 32 lanes.
        #pragma unroll
        for (int off = 16; off > 0; off >>= 1)
            acc += __shfl_down_sync(0xFFFFFFFFu, acc, off);
        if (lane == 0) out[(size_t)f * NLOC + a] = 0.5f * acc;
    }
}

extern "C" void kernel_launch(void* const* d_in, const int* in_sizes, int n_in,
                              void* d_out, int out_size)
{
    const float*  coord = (const float*)d_in[0];
    const int*    atype = (const int*)d_in[1];
    const int*    nlist = (const int*)d_in[2];
    const float4* tab   = (const float4*)d_in[3];
    float*        out   = (float*)d_out;

    // Opt-in to >48KB dynamic smem (idempotent; not a stream op, capture-safe).
    static bool attr_set = false;
    if (!attr_set) {
        cudaFuncSetAttribute(pairtab_kernel,
                             cudaFuncAttributeMaxDynamicSharedMemorySize,
                             SMEM_BYTES);
        attr_set = true;
    }

    pairtab_kernel<<<NFRAMES * BLOCKS_PER_FRAME, THREADS, SMEM_BYTES>>>(
        coord, atype, nlist, tab, out);
}

// round 11
// speedup vs baseline: 1.8830x; 1.0528x over previous
#include <cuda_runtime.h>

// PairTabModel: atomic energy via cubic-spline table lookup over neighbor lists.
// Shapes: coord (8,8192,3) f32, atype (8,8192) i32, nlist (8,4096,256) i32,
//         tab (4,4,1024,4) f32 -> out (8,4096) f32.
//
// Numerics (ulp-matched to reference, validated R1-R8, rel_err ~1.1e-7):
//   * s = (dx^2 + dz^2) + dy^2   (shuffle-tree horizontal reduce order)
//   * uu = rr * 50.0f            (div-by-const -> mul-by-reciprocal)
//   * sqrt.rn
// DO NOT alter the order/rounding of these ops (random spline table ->
// knot index is ulp-sensitive). Per-atom accumulation is smooth/reorderable.
//
// Perf structure:
//   R9 -> R10: frame coords+types staged in 128 KB smem; coord gather = LDS.128.
//   R10 -> R11: grid 128 -> 148 (one CTA per SM, was leaving 20 SMs idle).
//     Frames 0-3: 18 CTAs, frames 4-7: 19 CTAs; uneven atom ranges.

static constexpr int NFRAMES = 8;
static constexpr int NLOC    = 4096;
static constexpr int NALL    = 8192;
static constexpr int NNEI    = 256;
static constexpr int NTYPES  = 4;
static constexpr int NSPLINE = 1024;

static constexpr int THREADS = 1024;                       // 32 warps
static constexpr int GRID    = 148;                        // one CTA per SM
static constexpr unsigned SMEM_BYTES = NALL * sizeof(float4);  // 128 KB

__global__ __launch_bounds__(THREADS, 1)
void pairtab_kernel(const float*  __restrict__ coord,   // (NFRAMES, NALL, 3)
                    const int*    __restrict__ atype,   // (NFRAMES, NALL)
                    const int*    __restrict__ nlist,   // (NFRAMES, NLOC, NNEI)
                    const float4* __restrict__ tab,     // (NTYPES, NTYPES, NSPLINE) of float4
                    float*        __restrict__ out)     // (NFRAMES, NLOC)
{
    extern __shared__ float4 s_packed[];                 // [NALL]

    const int tid  = threadIdx.x;
    const int lane = tid & 31;
    const int w    = tid >> 5;
    const int bid  = blockIdx.x;

    // Block -> (frame, local index, #blocks in frame).
    // Frames 0-3: 18 blocks each (bids 0..71); frames 4-7: 19 blocks (72..147).
    int f, local, nb;
    if (bid < 72) { f = bid / 18;          local = bid % 18;        nb = 18; }
    else          { f = 4 + (bid - 72)/19; local = (bid - 72) % 19; nb = 19; }
    const int a_start = (local * NLOC) / nb;
    const int a_end   = ((local + 1) * NLOC) / nb;

    // Stage the whole frame: packed (x,y,z,atype) per atom. Coalesced.
    {
        const float* cb = coord + (size_t)f * NALL * 3;
        const int*   ab = atype + (size_t)f * NALL;
        for (int a = tid; a < NALL; a += THREADS) {
            s_packed[a] = make_float4(cb[3 * a + 0], cb[3 * a + 1],
                                      cb[3 * a + 2], __int_as_float(ab[a]));
        }
    }
    __syncthreads();

    // One warp per atom, warps stride over this CTA's atom range.
    for (int a = a_start + w; a < a_end; a += 32) {
        const float4 pi = s_packed[a];                   // LDS broadcast
        const int    it = __float_as_int(pi.w);
        const int* nrow = nlist + ((size_t)f * NLOC + a) * NNEI;
        const float4* tabi = tab + (size_t)it * NTYPES * NSPLINE;

        float acc = 0.f;
        #pragma unroll
        for (int c = 0; c < NNEI / 32; ++c) {
            const int n     = __ldg(&nrow[c * 32 + lane]);   // coalesced
            const bool valid = (n != -1);
            const int nm    = (n < 0) ? 0 : n;

            const float4 pj = s_packed[nm];              // LDS.128 gather
            const int    jt = __float_as_int(pj.w);

            // Shuffle-tree reduce order: (dx^2 + dz^2) + dy^2. No contraction.
            const float dx = __fsub_rn(pi.x, pj.x);
            const float dy = __fsub_rn(pi.y, pj.y);
            const float dz = __fsub_rn(pi.z, pj.z);
            const float s  = __fadd_rn(__fadd_rn(__fmul_rn(dx, dx),
                                                 __fmul_rn(dz, dz)),
                                       __fmul_rn(dy, dy));
            const float rr = __fsqrt_rn(s);

            // div-by-const -> mul by reciprocal; 1/0.02f == 50.0f exactly.
            const float uu = valid ? __fmul_rn(rr, 50.0f) : (float)(NSPLINE + 1);

            const int   idx  = (int)uu;                  // truncation, uu >= 0
            const float frac = __fsub_rn(uu, (float)idx);
            const int   clip = (idx > NSPLINE - 1) ? (NSPLINE - 1)
                                                   : (idx < 0 ? 0 : idx);

            float4 cc;
            if (idx >= NSPLINE) {
                cc = make_float4(0.f, 0.f, 0.f, 0.f);
            } else {
                cc = __ldg(&tabi[(size_t)jt * NSPLINE + clip]);  // L1/L2 gather
            }

            float ener = fmaf(fmaf(fmaf(cc.w, frac, cc.z), frac, cc.y), frac, cc.x);
            if (!valid) ener = 0.f;
            acc += ener;                                 // smooth sum
        }

        // Warp reduction over 32 lanes.
        #pragma unroll
        for (int off = 16; off > 0; off >>= 1)
            acc += __shfl_down_sync(0xFFFFFFFFu, acc, off);
        if (lane == 0) out[(size_t)f * NLOC + a] = 0.5f * acc;
    }
}

extern "C" void kernel_launch(void* const* d_in, const int* in_sizes, int n_in,
                              void* d_out, int out_size)
{
    const float*  coord = (const float*)d_in[0];
    const int*    atype = (const int*)d_in[1];
    const int*    nlist = (const int*)d_in[2];
    const float4* tab   = (const float4*)d_in[3];
    float*        out   = (float*)d_out;

    // Opt-in to >48KB dynamic smem (idempotent; not a stream op, capture-safe).
    static bool attr_set = false;
    if (!attr_set) {
        cudaFuncSetAttribute(pairtab_kernel,
                             cudaFuncAttributeMaxDynamicSharedMemorySize,
                             SMEM_BYTES);
        attr_set = true;
    }

    pairtab_kernel<<<GRID, THREADS, SMEM_BYTES>>>(coord, atype, nlist, tab, out);
}

// round 12
// speedup vs baseline: 1.9711x; 1.0468x over previous
#include <cuda_runtime.h>

// PairTabModel: atomic energy via cubic-spline table lookup over neighbor lists.
// Shapes: coord (8,8192,3) f32, atype (8,8192) i32, nlist (8,4096,256) i32,
//         tab (4,4,1024,4) f32 -> out (8,4096) f32.
//
// Numerics (ulp-matched to reference, validated R1-R8, rel_err ~1.1e-7):
//   * s = (dx^2 + dz^2) + dy^2   (shuffle-tree horizontal reduce order)
//   * uu = rr * 50.0f            (div-by-const -> mul-by-reciprocal)
//   * sqrt.rn
// DO NOT alter the order/rounding of these ops (random spline table ->
// knot index is ulp-sensitive). Per-atom accumulation is smooth/reorderable.
//
// Perf structure:
//   R10: frame coords+types in 128 KB smem (coord gather = LDS.128).
//   R11: grid 148, one CTA per SM.
//   R12: bucket CTAs by (frame, center-atom type): stage tab[it] (64 KB) in
//        smem too, so the spline-coef gather becomes LDS.128 instead of ~32
//        L1tex wavefronts. CTAs compact their type-matching atoms into a
//        smem list (order-independent).

static constexpr int NFRAMES = 8;
static constexpr int NLOC    = 4096;
static constexpr int NALL    = 8192;
static constexpr int NNEI    = 256;
static constexpr int NTYPES  = 4;
static constexpr int NSPLINE = 1024;

static constexpr int THREADS = 1024;                       // 32 warps
static constexpr int GRID    = 148;                        // one CTA per SM

// Dynamic smem layout (float4-aligned):
//   s_packed[NALL]            128 KB   packed (x,y,z,type) per atom
//   s_tab[NTYPES*NSPLINE]      64 KB   tab[it][jt][spline]
//   s_list[NLOC/4 rounded]      4 KB   compacted atom indices (<=1024)
//   s_count                     +16B
static constexpr unsigned SMEM_PACKED_ELEMS = NALL;                 // float4
static constexpr unsigned SMEM_TAB_ELEMS    = NTYPES * NSPLINE;     // float4
static constexpr unsigned SMEM_BYTES =
    (SMEM_PACKED_ELEMS + SMEM_TAB_ELEMS) * sizeof(float4)
    + 1024 * sizeof(int) + 16;

__global__ __launch_bounds__(THREADS, 1)
void pairtab_kernel(const float*  __restrict__ coord,   // (NFRAMES, NALL, 3)
                    const int*    __restrict__ atype,   // (NFRAMES, NALL)
                    const int*    __restrict__ nlist,   // (NFRAMES, NLOC, NNEI)
                    const float4* __restrict__ tab,     // (NTYPES, NTYPES, NSPLINE) of float4
                    float*        __restrict__ out)     // (NFRAMES, NLOC)
{
    extern __shared__ float4 smem[];
    float4* s_packed = smem;                             // [NALL]
    float4* s_tab    = smem + SMEM_PACKED_ELEMS;         // [NTYPES*NSPLINE]
    int*    s_list   = (int*)(smem + SMEM_PACKED_ELEMS + SMEM_TAB_ELEMS);
    int*    s_count  = s_list + 1024;

    const int tid  = threadIdx.x;
    const int lane = tid & 31;
    const int w    = tid >> 5;
    const int bid  = blockIdx.x;

    // Block -> (bucket, local slice, #CTAs in bucket).
    // Buckets 0..19: 5 CTAs each (bids 0..99); buckets 20..31: 4 CTAs (100..147).
    int bucket, local, ncta;
    if (bid < 100) { bucket = bid / 5;            local = bid % 5;         ncta = 5; }
    else           { bucket = 20 + (bid - 100)/4; local = (bid - 100) % 4; ncta = 4; }
    const int f  = bucket >> 2;                  // frame
    const int it = bucket & 3;                   // this CTA's center-atom type
    const int r0 = (local * NLOC) / ncta;        // candidate range [r0, r1)
    const int r1 = ((local + 1) * NLOC) / ncta;

    if (tid == 0) *s_count = 0;
    __syncthreads();

    const float* cb = coord + (size_t)f * NALL * 3;
    const int*   ab = atype + (size_t)f * NALL;

    // Stage the whole frame: packed (x,y,z,atype) per atom. Coalesced.
    for (int a = tid; a < NALL; a += THREADS) {
        s_packed[a] = make_float4(cb[3 * a + 0], cb[3 * a + 1],
                                  cb[3 * a + 2], __int_as_float(ab[a]));
    }
    // Stage tab[it] : (NTYPES, NSPLINE) float4 = 64 KB. Coalesced.
    {
        const float4* tsrc = tab + (size_t)it * NTYPES * NSPLINE;
        for (int e = tid; e < NTYPES * NSPLINE; e += THREADS)
            s_tab[e] = __ldg(&tsrc[e]);
    }
    // Compact this bucket's atoms (type == it) from the candidate slice.
    // Reads types from gmem (no dependence on s_packed staging order).
    for (int a = r0 + tid; a < r1; a += THREADS) {
        if (ab[a] == it) {
            int pos = atomicAdd(s_count, 1);
            s_list[pos] = a;
        }
    }
    __syncthreads();

    const int cnt = *s_count;

    // One warp per atom, warps stride over the compacted list.
    for (int k = w; k < cnt; k += 32) {
        const int a = s_list[k];
        const float4 pi = s_packed[a];                   // LDS broadcast
        const int* nrow = nlist + ((size_t)f * NLOC + a) * NNEI;

        float acc = 0.f;
        #pragma unroll
        for (int c = 0; c < NNEI / 32; ++c) {
            const int n     = __ldg(&nrow[c * 32 + lane]);   // coalesced
            const bool valid = (n != -1);
            const int nm    = (n < 0) ? 0 : n;

            const float4 pj = s_packed[nm];              // LDS.128 gather
            const int    jt = __float_as_int(pj.w);

            // Shuffle-tree reduce order: (dx^2 + dz^2) + dy^2. No contraction.
            const float dx = __fsub_rn(pi.x, pj.x);
            const float dy = __fsub_rn(pi.y, pj.y);
            const float dz = __fsub_rn(pi.z, pj.z);
            const float s  = __fadd_rn(__fadd_rn(__fmul_rn(dx, dx),
                                                 __fmul_rn(dz, dz)),
                                       __fmul_rn(dy, dy));
            const float rr = __fsqrt_rn(s);

            // div-by-const -> mul by reciprocal; 1/0.02f == 50.0f exactly.
            const float uu = valid ? __fmul_rn(rr, 50.0f) : (float)(NSPLINE + 1);

            const int   idx  = (int)uu;                  // truncation, uu >= 0
            const float frac = __fsub_rn(uu, (float)idx);
            const int   clip = (idx > NSPLINE - 1) ? (NSPLINE - 1)
                                                   : (idx < 0 ? 0 : idx);

            // Spline coefficients from smem (always-safe load, then select).
            const float4 ct = s_tab[jt * NSPLINE + clip];    // LDS.128 gather
            const bool live = (idx < NSPLINE);
            const float c0 = live ? ct.x : 0.f;
            const float c1 = live ? ct.y : 0.f;
            const float c2 = live ? ct.z : 0.f;
            const float c3 = live ? ct.w : 0.f;

            float ener = fmaf(fmaf(fmaf(c3, frac, c2), frac, c1), frac, c0);
            if (!valid) ener = 0.f;
            acc += ener;                                 // smooth sum
        }

        // Warp reduction over 32 lanes.
        #pragma unroll
        for (int off = 16; off > 0; off >>= 1)
            acc += __shfl_down_sync(0xFFFFFFFFu, acc, off);
        if (lane == 0) out[(size_t)f * NLOC + a] = 0.5f * acc;
    }
}

extern "C" void kernel_launch(void* const* d_in, const int* in_sizes, int n_in,
                              void* d_out, int out_size)
{
    const float*  coord = (const float*)d_in[0];
    const int*    atype = (const int*)d_in[1];
    const int*    nlist = (const int*)d_in[2];
    const float4* tab   = (const float4*)d_in[3];
    float*        out   = (float*)d_out;

    // Opt-in to >48KB dynamic smem (idempotent; not a stream op, capture-safe).
    static bool attr_set = false;
    if (!attr_set) {
        cudaFuncSetAttribute(pairtab_kernel,
                             cudaFuncAttributeMaxDynamicSharedMemorySize,
                             SMEM_BYTES);
        attr_set = true;
    }

    pairtab_kernel<<<GRID, THREADS, SMEM_BYTES>>>(coord, atype, nlist, tab, out);
}